// round 16
// baseline (speedup 1.0000x reference)
#include <cuda_runtime.h>
#include <cstdint>

typedef unsigned long long ULL;

// Problem constants: B=128, T=1024, H=128, D=64, L=3
#define BB   128
#define TT   1024
#define HH   128
#define G4   512
#define MROWS (BB*TT)
#define CHUNK 128
#define NCHUNK 8

// Scratch (device globals: allocation-rule-safe)
__device__ float g_xg[(size_t)MROWS * G4];    // 256 MB (recycled per layer-chunk)
__device__ float g_y [(size_t)MROWS * HH];    // 64 MB  (recycled per layer-chunk)
__device__ float g_whl[3][512 * 128 * 2];     // per-layer Wih as interleaved (hi,lo)

// ---------------------------------------------------------------------------
// helpers
// ---------------------------------------------------------------------------
__device__ __forceinline__ void fma2(ULL& acc, ULL a, ULL b) {
    asm("fma.rn.f32x2 %0, %1, %2, %0;" : "+l"(acc) : "l"(a), "l"(b));
}
__device__ __forceinline__ void upk2(ULL v, float& lo, float& hi) {
    asm("mov.b64 {%0, %1}, %2;" : "=f"(lo), "=f"(hi) : "l"(v));
}
__device__ __forceinline__ float tanhapx(float x) {
    float y; asm("tanh.approx.f32 %0, %1;" : "=f"(y) : "f"(x)); return y;
}
__device__ __forceinline__ float sigapx(float x) {
    return fmaf(tanhapx(0.5f * x), 0.5f, 0.5f);
}
__device__ __forceinline__ uint32_t smem_u32(const void* p) {
    uint32_t a;
    asm("{ .reg .u64 t; cvta.to.shared.u64 t, %1; cvt.u32.u64 %0, t; }"
        : "=r"(a) : "l"(p));
    return a;
}
__device__ __forceinline__ uint32_t mapa_u32(uint32_t a, uint32_t rank) {
    uint32_t r;
    asm("mapa.shared::cluster.u32 %0, %1, %2;" : "=r"(r) : "r"(a), "r"(rank));
    return r;
}
__device__ __forceinline__ uint32_t f2tf32(float v) {
    uint32_t r; asm("cvt.rna.tf32.f32 %0, %1;" : "=r"(r) : "f"(v)); return r;
}
__device__ __forceinline__ void mma_tf32(float& c0, float& c1, float& c2, float& c3,
                                         uint32_t a0, uint32_t a1, uint32_t a2, uint32_t a3,
                                         uint32_t b0, uint32_t b1) {
    asm("mma.sync.aligned.m16n8k8.row.col.f32.tf32.tf32.f32 "
        "{%0,%1,%2,%3},{%4,%5,%6,%7},{%8,%9},{%0,%1,%2,%3};"
        : "+f"(c0), "+f"(c1), "+f"(c2), "+f"(c3)
        : "r"(a0), "r"(a1), "r"(a2), "r"(a3), "r"(b0), "r"(b1));
}

// ---------------------------------------------------------------------------
// init: copy h0,c0 -> state arrays
// ---------------------------------------------------------------------------
__global__ void init_state(const float* __restrict__ h0,
                           const float* __restrict__ c0,
                           float* __restrict__ hN, float* __restrict__ cN)
{
    int i = blockIdx.x * blockDim.x + threadIdx.x;
    if (i < 3 * BB * HH) { hN[i] = h0[i]; cN[i] = c0[i]; }
}

// ---------------------------------------------------------------------------
// w_conv: W[512*K] -> g_whl[l] interleaved (hi, lo)
// ---------------------------------------------------------------------------
__global__ void w_conv(const float* __restrict__ W, int l, int n)
{
    int i = blockIdx.x * blockDim.x + threadIdx.x;
    if (i < n) {
        float v = W[i];
        float h = __uint_as_float(f2tf32(v));
        g_whl[l][2 * i]     = h;
        g_whl[l][2 * i + 1] = v - h;
    }
}

// ---------------------------------------------------------------------------
// 3xTF32 tensor-core GEMM (verbatim from R13/R15 — passing).
// ---------------------------------------------------------------------------
template<int K>
__global__ __launch_bounds__(256, 2)
void xg_tf32(const float* __restrict__ Aext, int use_gy, int layer,
             const float* __restrict__ bih,
             const float* __restrict__ bhh,
             int t0, int lg)
{
    __shared__ float Ahl[2][128][9][2];
    __shared__ float Bhl[2][128][9][2];

    const float* A   = use_gy ? (const float*)g_y : Aext;
    const float* Whl = g_whl[layer];

    const int tid  = threadIdx.x;
    const int lane = tid & 31;
    const int warp = tid >> 5;
    const int wm   = warp & 1;
    const int wn   = warp >> 1;
    const int gq   = lane >> 2;
    const int tq   = lane & 3;

    const int m0 = ((blockIdx.y >> lg) * TT) + t0 +
                   ((blockIdx.y & ((1 << lg) - 1)) * 128);
    const int n0 = blockIdx.x * 128;

    const int srow = tid >> 1;
    const int skk  = (tid & 1) * 4;

    float acc[4][4][4];
#pragma unroll
    for (int i = 0; i < 4; i++)
#pragma unroll
        for (int j = 0; j < 4; j++)
#pragma unroll
            for (int q = 0; q < 4; q++) acc[i][j][q] = 0.f;

    float bias[4][2];
#pragma unroll
    for (int nt = 0; nt < 4; nt++) {
        int col = n0 + wn * 32 + nt * 8 + tq * 2;
        bias[nt][0] = bih[col] + bhh[col];
        bias[nt][1] = bih[col + 1] + bhh[col + 1];
    }

    {
        float4 av = *(const float4*)(A + (size_t)(m0 + srow) * K + skk);
        const float aa[4] = {av.x, av.y, av.z, av.w};
#pragma unroll
        for (int j = 0; j < 4; j++) {
            float h = __uint_as_float(f2tf32(aa[j]));
            *(float2*)&Ahl[0][srow][skk + j][0] = make_float2(h, aa[j] - h);
        }
        const float4* wv = (const float4*)(Whl + ((size_t)(n0 + srow) * K + skk) * 2);
        float4 w0 = wv[0], w1 = wv[1];
        *(float2*)&Bhl[0][srow][skk + 0][0] = make_float2(w0.x, w0.y);
        *(float2*)&Bhl[0][srow][skk + 1][0] = make_float2(w0.z, w0.w);
        *(float2*)&Bhl[0][srow][skk + 2][0] = make_float2(w1.x, w1.y);
        *(float2*)&Bhl[0][srow][skk + 3][0] = make_float2(w1.z, w1.w);
    }
    __syncthreads();

    const int NC = K / 8;
    for (int c = 0; c < NC; ++c) {
        const int cur = c & 1, nxt = cur ^ 1;
        float aa[4];
        float4 w0, w1;
        if (c + 1 < NC) {
            float4 av = *(const float4*)(A + (size_t)(m0 + srow) * K + (c + 1) * 8 + skk);
            aa[0] = av.x; aa[1] = av.y; aa[2] = av.z; aa[3] = av.w;
            const float4* wv = (const float4*)(Whl +
                ((size_t)(n0 + srow) * K + (c + 1) * 8 + skk) * 2);
            w0 = wv[0]; w1 = wv[1];
        }

        uint32_t bh[4][2], bl[4][2];
#pragma unroll
        for (int nt = 0; nt < 4; nt++) {
            int nr = wn * 32 + nt * 8 + gq;
            float2 v0 = *(const float2*)&Bhl[cur][nr][tq][0];
            float2 v1 = *(const float2*)&Bhl[cur][nr][tq + 4][0];
            bh[nt][0] = __float_as_uint(v0.x); bl[nt][0] = __float_as_uint(v0.y);
            bh[nt][1] = __float_as_uint(v1.x); bl[nt][1] = __float_as_uint(v1.y);
        }
#pragma unroll
        for (int mt = 0; mt < 4; mt++) {
            int mr = wm * 64 + mt * 16 + gq;
            float2 u0 = *(const float2*)&Ahl[cur][mr][tq][0];
            float2 u1 = *(const float2*)&Ahl[cur][mr + 8][tq][0];
            float2 u2 = *(const float2*)&Ahl[cur][mr][tq + 4][0];
            float2 u3 = *(const float2*)&Ahl[cur][mr + 8][tq + 4][0];
            uint32_t ah0 = __float_as_uint(u0.x), al0 = __float_as_uint(u0.y);
            uint32_t ah1 = __float_as_uint(u1.x), al1 = __float_as_uint(u1.y);
            uint32_t ah2 = __float_as_uint(u2.x), al2 = __float_as_uint(u2.y);
            uint32_t ah3 = __float_as_uint(u3.x), al3 = __float_as_uint(u3.y);
#pragma unroll
            for (int nt = 0; nt < 4; nt++) {
                float* cc = acc[mt][nt];
                mma_tf32(cc[0], cc[1], cc[2], cc[3],
                         ah0, ah1, ah2, ah3, bh[nt][0], bh[nt][1]);
                mma_tf32(cc[0], cc[1], cc[2], cc[3],
                         ah0, ah1, ah2, ah3, bl[nt][0], bl[nt][1]);
                mma_tf32(cc[0], cc[1], cc[2], cc[3],
                         al0, al1, al2, al3, bh[nt][0], bh[nt][1]);
            }
        }

        if (c + 1 < NC) {
#pragma unroll
            for (int j = 0; j < 4; j++) {
                float h = __uint_as_float(f2tf32(aa[j]));
                *(float2*)&Ahl[nxt][srow][skk + j][0] = make_float2(h, aa[j] - h);
            }
            *(float2*)&Bhl[nxt][srow][skk + 0][0] = make_float2(w0.x, w0.y);
            *(float2*)&Bhl[nxt][srow][skk + 1][0] = make_float2(w0.z, w0.w);
            *(float2*)&Bhl[nxt][srow][skk + 2][0] = make_float2(w1.x, w1.y);
            *(float2*)&Bhl[nxt][srow][skk + 3][0] = make_float2(w1.z, w1.w);
            __syncthreads();
        }
    }

#pragma unroll
    for (int mt = 0; mt < 4; mt++) {
        int row0 = m0 + wm * 64 + mt * 16 + gq;
#pragma unroll
        for (int nt = 0; nt < 4; nt++) {
            int col = n0 + wn * 32 + nt * 8 + tq * 2;
            float* cc = acc[mt][nt];
            *(float2*)(g_xg + (size_t)row0 * G4 + col) =
                make_float2(cc[0] + bias[nt][0], cc[1] + bias[nt][1]);
            *(float2*)(g_xg + (size_t)(row0 + 8) * G4 + col) =
                make_float2(cc[2] + bias[nt][0], cc[3] + bias[nt][1]);
        }
    }
}

// ---------------------------------------------------------------------------
// Recurrent chunk v16: R13 proven skeleton, landing buffer removed — gate
// warps DSMEM-store h directly into the peer's hbuf[pw] at their own column
// (same offset as local). Parity reuse separated by 2 steps via the h chain.
// ---------------------------------------------------------------------------
__global__ __launch_bounds__(512, 1) __cluster_dims__(2, 1, 1)
void lstm_rec16(const float* __restrict__ whh0,
                const float* __restrict__ whh1,
                const float* __restrict__ whh2,
                float* __restrict__ hN, float* __restrict__ cN,
                int4 lsel, int4 tsel)
{
    __shared__ __align__(16) float hbuf[2][4][132];
    __shared__ __align__(16) float pre[2][256][4];
    __shared__ __align__(8)  ULL   bar;

    const int lc = blockIdx.y;
    const int l  = (lc == 0) ? lsel.x : (lc == 1) ? lsel.y : lsel.z;
    const int t0 = (lc == 0) ? tsel.x : (lc == 1) ? tsel.y : tsel.z;
    const float* whh = (l == 0) ? whh0 : (l == 1) ? whh1 : whh2;
    float* hstate = hN + l * BB * HH;
    float* cstate = cN + l * BB * HH;

    const int tid = threadIdx.x;
    const int r   = blockIdx.x & 1;
    const int b0  = (blockIdx.x >> 1) * 4;

    const int kh = tid >> 8;
    const int jp = tid & 255;
    const int g  = jp >> 6;
    const int nn = jp & 63;

    uint32_t bar_addr = smem_u32(&bar);
    uint32_t peer_bar = mapa_u32(bar_addr, (uint32_t)(r ^ 1));

    if (tid == 0) {
        asm volatile("mbarrier.init.shared.b64 [%0], %1;"
                     :: "r"(bar_addr), "r"(8) : "memory");
    }
    {
        int row = tid >> 7, n = tid & 127;
        hbuf[1][row][n] = hstate[(b0 + row) * HH + n];
    }

    const int row_w = g * 128 + r * 64 + nn;
    ULL w2[32];
    const ULL* wp = (const ULL*)(whh + (size_t)row_w * HH + kh * 64);
#pragma unroll
    for (int i = 0; i < 32; i++) w2[i] = wp[i];

    const bool is_gate = (kh == (r ^ 1));
    const int row_g = jp & 3;
    const int nn_g  = jp >> 2;
    const int n_g   = r * 64 + nn_g;

    float c = 0.f, hlast = 0.f;
    const float* px = g_xg + ((size_t)(b0 + row_g) * TT) * G4 + n_g;
    float*       py = g_y  + ((size_t)(b0 + row_g) * TT) * HH + n_g;
    uint32_t pl0 = 0, pl1 = 0;   // peer hbuf slots (our column, their buffer)
    float xc0=0,xc1=0,xc2=0,xc3=0, xn0=0,xn1=0,xn2=0,xn3=0;
    if (is_gate) {
        c   = cstate[(b0 + row_g) * HH + n_g];
        pl0 = mapa_u32(smem_u32(&hbuf[0][row_g][n_g]), (uint32_t)(r ^ 1));
        pl1 = mapa_u32(smem_u32(&hbuf[1][row_g][n_g]), (uint32_t)(r ^ 1));
        const float* p0 = px + (size_t)t0 * G4;
        xc0 = p0[0];        xc1 = p0[128];        xc2 = p0[256];        xc3 = p0[384];
        xn0 = p0[G4 + 0];   xn1 = p0[G4 + 128];   xn2 = p0[G4 + 256];   xn3 = p0[G4 + 384];
    }

    __syncthreads();
    asm volatile("barrier.cluster.arrive.aligned;" ::: "memory");
    asm volatile("barrier.cluster.wait.aligned;"   ::: "memory");

    for (int s = 0; s < CHUNK; ++s) {
        const int t  = t0 + s;
        const int pr = (s + 1) & 1;
        const int pw = s & 1;

        float s4[4];
#pragma unroll
        for (int rr = 0; rr < 4; rr += 2) {
            ULL a0 = 0, a1 = 0, c0_ = 0, c1_ = 0;
            const ulonglong2* hA = (const ulonglong2*)&hbuf[pr][rr][kh * 64];
            const ulonglong2* hB = (const ulonglong2*)&hbuf[pr][rr + 1][kh * 64];
#pragma unroll
            for (int i = 0; i < 16; i++) {
                ulonglong2 uA = hA[i], uB = hB[i];
                fma2(a0,  w2[2 * i],     uA.x);
                fma2(a1,  w2[2 * i + 1], uA.y);
                fma2(c0_, w2[2 * i],     uB.x);
                fma2(c1_, w2[2 * i + 1], uB.y);
            }
            float x0, x1, x2, x3;
            upk2(a0, x0, x1); upk2(a1, x2, x3);
            s4[rr] = (x0 + x1) + (x2 + x3);
            upk2(c0_, x0, x1); upk2(c1_, x2, x3);
            s4[rr + 1] = (x0 + x1) + (x2 + x3);
        }
        *(float4*)&pre[kh][jp][0] = make_float4(s4[0], s4[1], s4[2], s4[3]);
        __syncthreads();

        if (is_gate) {
            float pi = pre[0][      nn_g][row_g] + pre[1][      nn_g][row_g];
            float pf = pre[0][ 64 + nn_g][row_g] + pre[1][ 64 + nn_g][row_g];
            float pg = pre[0][128 + nn_g][row_g] + pre[1][128 + nn_g][row_g];
            float po = pre[0][192 + nn_g][row_g] + pre[1][192 + nn_g][row_g];
            float iv = sigapx(pi + xc0);
            float fv = sigapx(pf + xc1);
            float gv = tanhapx(pg + xc2);
            float ov = sigapx(po + xc3);
            c = fv * c + iv * gv;
            float hh = ov * tanhapx(c);
            hlast = hh;
            uint32_t pa = pw ? pl1 : pl0;
            asm volatile("st.shared::cluster.f32 [%0], %1;"
                         :: "r"(pa), "f"(hh) : "memory");
            hbuf[pw][row_g][n_g] = hh;
            __syncwarp();
            if ((tid & 31) == 0) {
                asm volatile("mbarrier.arrive.release.cluster.shared::cluster.b64 _, [%0];"
                             :: "r"(peer_bar) : "memory");
            }
            {
                unsigned par = (unsigned)(s & 1);
                asm volatile(
                    "{\n\t"
                    ".reg .pred P1;\n\t"
                    "WLP%=:\n\t"
                    "mbarrier.try_wait.parity.acquire.cluster.shared::cta.b64 P1, [%0], %1, 0x989680;\n\t"
                    "@!P1 bra WLP%=;\n\t"
                    "}"
                    :: "r"(bar_addr), "r"(par) : "memory");
            }
            // peer's DSMEM stores landed directly in hbuf[pw] peer half
        }
        __syncthreads();

        if (is_gate) {
            py[(size_t)t * HH] = hlast;
            float xf0 = 0, xf1 = 0, xf2 = 0, xf3 = 0;
            if (s + 2 < CHUNK) {
                const float* p2 = px + (size_t)(t + 2) * G4;
                xf0 = p2[0]; xf1 = p2[128]; xf2 = p2[256]; xf3 = p2[384];
            }
            xc0 = xn0; xc1 = xn1; xc2 = xn2; xc3 = xn3;
            xn0 = xf0; xn1 = xf1; xn2 = xf2; xn3 = xf3;
        }
    }

    if (is_gate) {
        hstate[(b0 + row_g) * HH + n_g] = hlast;
        cstate[(b0 + row_g) * HH + n_g] = c;
    }
    asm volatile("barrier.cluster.arrive.aligned;" ::: "memory");
    asm volatile("barrier.cluster.wait.aligned;"   ::: "memory");
}

// ---------------------------------------------------------------------------
// Chunked output projection: rows b*TT + t0 + [0,CHUNK)
// ---------------------------------------------------------------------------
__global__ __launch_bounds__(256)
void proj_chunk(const float* __restrict__ wout,
                const float* __restrict__ bout,
                float* __restrict__ out, int t0)
{
    int gw   = (blockIdx.x * blockDim.x + threadIdx.x) >> 5;  // 0..BB*CHUNK-1
    int lane = threadIdx.x & 31;
    if (gw >= BB * CHUNK) return;
    int b = gw >> 7;                 // CHUNK = 128
    int t = gw & 127;
    size_t row = (size_t)b * TT + t0 + t;
    float4 yv = ((const float4*)(g_y + row * HH))[lane];
    float4 wv = ((const float4*)wout)[lane];
    float s = yv.x * wv.x + yv.y * wv.y + yv.z * wv.z + yv.w * wv.w;
#pragma unroll
    for (int o = 16; o; o >>= 1) s += __shfl_xor_sync(0xFFFFFFFFu, s, o);
    if (lane == 0) out[row] = fmaxf(s + bout[0], 0.f);
}

// ---------------------------------------------------------------------------
// R15 schedule + prologue reorg + chunked proj overlap.
// Walls: w0:(0,0) w1:(0,1)(1,0) w2:(0,2)(1,1) w3:(0,3)(2,0) w4:(0,4)(1,2)
//  w5:(0,5)(2,1) w6:(0,6)(1,3) w7:(0,7)(2,2) w8:(1,4)(2,3) w9:(1,5)(2,4)
//  w10:(1,6)(2,5) w11:(1,7)(2,6) w12:(2,7)
// proj(c) producer walls: c0:w3 c1:w5 c2:w7 c3:w8 c4:w9 c5:w10 c6:w11 c7:w12.
// ---------------------------------------------------------------------------
extern "C" void kernel_launch(void* const* d_in, const int* in_sizes, int n_in,
                              void* d_out, int out_size)
{
    const float* x    = (const float*)d_in[0];
    const float* h0   = (const float*)d_in[1];
    const float* c0   = (const float*)d_in[2];
    const float* Wih[3] = {(const float*)d_in[3], (const float*)d_in[7],  (const float*)d_in[11]};
    const float* Whh[3] = {(const float*)d_in[4], (const float*)d_in[8],  (const float*)d_in[12]};
    const float* bih[3] = {(const float*)d_in[5], (const float*)d_in[9],  (const float*)d_in[13]};
    const float* bhh[3] = {(const float*)d_in[6], (const float*)d_in[10], (const float*)d_in[14]};
    const float* Wout = (const float*)d_in[15];
    const float* bout = (const float*)d_in[16];

    float* out = (float*)d_out;
    float* hN  = out + MROWS;
    float* cN  = hN + 3 * BB * HH;

    static cudaStream_t s2 = nullptr;
    static cudaEvent_t evPre, evWc, evPj, evW[13], evG0[8], evC[13];
    if (!s2) {
        cudaStreamCreateWithFlags(&s2, cudaStreamNonBlocking);
        cudaEventCreateWithFlags(&evPre, cudaEventDisableTiming);
        cudaEventCreateWithFlags(&evWc,  cudaEventDisableTiming);
        cudaEventCreateWithFlags(&evPj,  cudaEventDisableTiming);
        for (int i = 0; i < 13; i++) {
            cudaEventCreateWithFlags(&evW[i], cudaEventDisableTiming);
            cudaEventCreateWithFlags(&evC[i], cudaEventDisableTiming);
        }
        for (int i = 0; i < 8; i++)
            cudaEventCreateWithFlags(&evG0[i], cudaEventDisableTiming);
    }

    const int C = CHUNK;
    auto rec1 = [&](int l0_, int t0_) {
        lstm_rec16<<<dim3(64, 1), 512>>>(Whh[0], Whh[1], Whh[2], hN, cN,
                                         make_int4(l0_, 0, 0, 0),
                                         make_int4(t0_, 0, 0, 0));
    };
    auto rec2 = [&](int la, int ta, int lb, int tb) {
        lstm_rec16<<<dim3(64, 2), 512>>>(Whh[0], Whh[1], Whh[2], hN, cN,
                                         make_int4(la, lb, 0, 0),
                                         make_int4(ta, tb, 0, 0));
    };
    auto gemmM = [&](int l, int cc) {
        xg_tf32<128><<<dim3(4, 128), 256>>>(nullptr, 1, l, bih[l], bhh[l],
                                            cc * C, 0);
    };
    auto gemmS = [&](int l, int cc) {
        xg_tf32<128><<<dim3(4, 128), 256, 0, s2>>>(nullptr, 1, l, bih[l],
                                                   bhh[l], cc * C, 0);
    };
    auto gemm0S = [&](int cc) {
        xg_tf32<64><<<dim3(4, 128), 256, 0, s2>>>(x, 0, 0, bih[0], bhh[0],
                                                  cc * C, 0);
    };
    auto projS = [&](int cc) {
        proj_chunk<<<BB * C / 8, 256, 0, s2>>>(Wout, bout, out, cc * C);
    };

    // prologue: main does only what's needed for w0
    init_state<<<(3 * BB * HH + 511) / 512, 512>>>(h0, c0, hN, cN);
    w_conv<<<(512 * 64 + 255) / 256, 256>>>(Wih[0], 0, 512 * 64);
    cudaEventRecord(evPre, 0);
    xg_tf32<64><<<dim3(4, 128), 256>>>(x, 0, 0, bih[0], bhh[0], 0, 0); // g0(0)

    // side stream: layer-1/2 weight conversion + remaining layer-0 gemms
    cudaStreamWaitEvent(s2, evPre, 0);
    w_conv<<<(512 * 128 + 255) / 256, 256, 0, s2>>>(Wih[1], 1, 512 * 128);
    w_conv<<<(512 * 128 + 255) / 256, 256, 0, s2>>>(Wih[2], 2, 512 * 128);
    cudaEventRecord(evWc, s2);
    for (int cc = 1; cc < 8; cc++) { gemm0S(cc); cudaEventRecord(evG0[cc], s2); }

    // ---- walls ----
    rec1(0, 0);                                   // w0
    cudaStreamWaitEvent(0, evWc, 0);
    gemmM(1, 0);                                  // serial (gap 0)
    cudaStreamWaitEvent(0, evG0[1], 0);
    rec2(0, 1 * C, 1, 0 * C);                     // w1
    cudaEventRecord(evW[1], 0);
    gemmM(1, 1);                                  // serial (gap 0)

    cudaStreamWaitEvent(s2, evW[1], 0);
    gemmS(2, 0); cudaEventRecord(evC[3], s2);

    cudaStreamWaitEvent(0, evG0[2], 0);
    rec2(0, 2 * C, 1, 1 * C);                     // w2
    cudaEventRecord(evW[2], 0);

    cudaStreamWaitEvent(s2, evW[2], 0);
    gemmS(1, 2); cudaEventRecord(evC[4], s2);
    gemmS(2, 1); cudaEventRecord(evC[5], s2);

    cudaStreamWaitEvent(0, evG0[3], 0);
    cudaStreamWaitEvent(0, evC[3], 0);
    rec2(0, 3 * C, 2, 0 * C);                     // w3
    cudaEventRecord(evW[3], 0);

    cudaStreamWaitEvent(s2, evW[3], 0);
    gemmS(1, 3); cudaEventRecord(evC[6], s2);

    cudaStreamWaitEvent(0, evG0[4], 0);
    cudaStreamWaitEvent(0, evC[4], 0);
    rec2(0, 4 * C, 1, 2 * C);                     // w4
    cudaEventRecord(evW[4], 0);

    cudaStreamWaitEvent(s2, evW[4], 0);
    gemmS(2, 2); cudaEventRecord(evC[7], s2);
    gemmS(1, 4);                                  // covered by evC[8]

    cudaStreamWaitEvent(0, evG0[5], 0);
    cudaStreamWaitEvent(0, evC[5], 0);
    rec2(0, 5 * C, 2, 1 * C);                     // w5
    cudaEventRecord(evW[5], 0);

    cudaStreamWaitEvent(s2, evW[5], 0);
    gemmS(1, 5); cudaEventRecord(evC[9], s2);

    cudaStreamWaitEvent(0, evG0[6], 0);
    cudaStreamWaitEvent(0, evC[6], 0);
    rec2(0, 6 * C, 1, 3 * C);                     // w6
    cudaEventRecord(evW[6], 0);

    cudaStreamWaitEvent(s2, evW[6], 0);
    gemmS(2, 3); cudaEventRecord(evC[8], s2);     // also covers g(1,4)
    gemmS(1, 6); cudaEventRecord(evC[10], s2);

    cudaStreamWaitEvent(0, evG0[7], 0);
    cudaStreamWaitEvent(0, evC[7], 0);
    rec2(0, 7 * C, 2, 2 * C);                     // w7
    cudaEventRecord(evW[7], 0);

    cudaStreamWaitEvent(s2, evW[7], 0);
    gemmS(1, 7); cudaEventRecord(evC[11], s2);

    // side stream: overlapped projection chunks 0..6 (after all gemmS)
    cudaStreamWaitEvent(s2, evW[3], 0);  projS(0);
    cudaStreamWaitEvent(s2, evW[5], 0);  projS(1);
    // chunks 2..6 gated below as walls complete

    cudaStreamWaitEvent(0, evC[8], 0);
    rec2(1, 4 * C, 2, 3 * C);                     // w8
    cudaEventRecord(evW[8], 0);
    gemmM(2, 4);                                  // serial (gap 0)

    cudaStreamWaitEvent(s2, evW[7], 0);  projS(2);
    cudaStreamWaitEvent(s2, evW[8], 0);  projS(3);

    cudaStreamWaitEvent(0, evC[9], 0);
    rec2(1, 5 * C, 2, 4 * C);                     // w9
    cudaEventRecord(evW[9], 0);
    gemmM(2, 5);

    cudaStreamWaitEvent(s2, evW[9], 0);  projS(4);

    cudaStreamWaitEvent(0, evC[10], 0);
    rec2(1, 6 * C, 2, 5 * C);                     // w10
    cudaEventRecord(evW[10], 0);
    gemmM(2, 6);

    cudaStreamWaitEvent(s2, evW[10], 0); projS(5);

    cudaStreamWaitEvent(0, evC[11], 0);
    rec2(1, 7 * C, 2, 6 * C);                     // w11
    cudaEventRecord(evW[11], 0);
    gemmM(2, 7);

    cudaStreamWaitEvent(s2, evW[11], 0); projS(6);
    cudaEventRecord(evPj, s2);                    // last s2 node -> join below

    rec1(2, 7 * C);                               // w12

    cudaStreamWaitEvent(0, evPj, 0);              // join side stream
    proj_chunk<<<BB * C / 8, 256>>>(Wout, bout, out, 7 * C);  // proj(7)
}

// round 17
// speedup vs baseline: 1.0134x; 1.0134x over previous
#include <cuda_runtime.h>
#include <cstdint>

typedef unsigned long long ULL;

// Problem constants: B=128, T=1024, H=128, D=64, L=3
#define BB   128
#define TT   1024
#define HH   128
#define G4   512
#define MROWS (BB*TT)
#define CHUNK 128
#define NCHUNK 8

// Scratch (device globals: allocation-rule-safe)
__device__ float g_xg[(size_t)MROWS * G4];    // 256 MB (recycled per layer-chunk)
__device__ float g_y [(size_t)MROWS * HH];    // 64 MB  (recycled per layer-chunk)
__device__ float g_whl[3][512 * 128 * 2];     // per-layer Wih as interleaved (hi,lo)

// ---------------------------------------------------------------------------
// helpers
// ---------------------------------------------------------------------------
__device__ __forceinline__ void fma2(ULL& acc, ULL a, ULL b) {
    asm("fma.rn.f32x2 %0, %1, %2, %0;" : "+l"(acc) : "l"(a), "l"(b));
}
__device__ __forceinline__ void upk2(ULL v, float& lo, float& hi) {
    asm("mov.b64 {%0, %1}, %2;" : "=f"(lo), "=f"(hi) : "l"(v));
}
__device__ __forceinline__ float tanhapx(float x) {
    float y; asm("tanh.approx.f32 %0, %1;" : "=f"(y) : "f"(x)); return y;
}
__device__ __forceinline__ float sigapx(float x) {
    return fmaf(tanhapx(0.5f * x), 0.5f, 0.5f);
}
__device__ __forceinline__ uint32_t smem_u32(const void* p) {
    uint32_t a;
    asm("{ .reg .u64 t; cvta.to.shared.u64 t, %1; cvt.u32.u64 %0, t; }"
        : "=r"(a) : "l"(p));
    return a;
}
__device__ __forceinline__ uint32_t mapa_u32(uint32_t a, uint32_t rank) {
    uint32_t r;
    asm("mapa.shared::cluster.u32 %0, %1, %2;" : "=r"(r) : "r"(a), "r"(rank));
    return r;
}
__device__ __forceinline__ uint32_t f2tf32(float v) {
    uint32_t r; asm("cvt.rna.tf32.f32 %0, %1;" : "=r"(r) : "f"(v)); return r;
}
__device__ __forceinline__ void mma_tf32(float& c0, float& c1, float& c2, float& c3,
                                         uint32_t a0, uint32_t a1, uint32_t a2, uint32_t a3,
                                         uint32_t b0, uint32_t b1) {
    asm("mma.sync.aligned.m16n8k8.row.col.f32.tf32.tf32.f32 "
        "{%0,%1,%2,%3},{%4,%5,%6,%7},{%8,%9},{%0,%1,%2,%3};"
        : "+f"(c0), "+f"(c1), "+f"(c2), "+f"(c3)
        : "r"(a0), "r"(a1), "r"(a2), "r"(a3), "r"(b0), "r"(b1));
}

// ---------------------------------------------------------------------------
// init: copy h0,c0 -> state arrays
// ---------------------------------------------------------------------------
__global__ void init_state(const float* __restrict__ h0,
                           const float* __restrict__ c0,
                           float* __restrict__ hN, float* __restrict__ cN)
{
    int i = blockIdx.x * blockDim.x + threadIdx.x;
    if (i < 3 * BB * HH) { hN[i] = h0[i]; cN[i] = c0[i]; }
}

// ---------------------------------------------------------------------------
// w_conv: W[512*K] -> g_whl[l] interleaved (hi, lo)
// ---------------------------------------------------------------------------
__global__ void w_conv(const float* __restrict__ W, int l, int n)
{
    int i = blockIdx.x * blockDim.x + threadIdx.x;
    if (i < n) {
        float v = W[i];
        float h = __uint_as_float(f2tf32(v));
        g_whl[l][2 * i]     = h;
        g_whl[l][2 * i + 1] = v - h;
    }
}

// ---------------------------------------------------------------------------
// 3xTF32 tensor-core GEMM (verbatim — passing).
// ---------------------------------------------------------------------------
template<int K>
__global__ __launch_bounds__(256, 2)
void xg_tf32(const float* __restrict__ Aext, int use_gy, int layer,
             const float* __restrict__ bih,
             const float* __restrict__ bhh,
             int t0, int lg)
{
    __shared__ float Ahl[2][128][9][2];
    __shared__ float Bhl[2][128][9][2];

    const float* A   = use_gy ? (const float*)g_y : Aext;
    const float* Whl = g_whl[layer];

    const int tid  = threadIdx.x;
    const int lane = tid & 31;
    const int warp = tid >> 5;
    const int wm   = warp & 1;
    const int wn   = warp >> 1;
    const int gq   = lane >> 2;
    const int tq   = lane & 3;

    const int m0 = ((blockIdx.y >> lg) * TT) + t0 +
                   ((blockIdx.y & ((1 << lg) - 1)) * 128);
    const int n0 = blockIdx.x * 128;

    const int srow = tid >> 1;
    const int skk  = (tid & 1) * 4;

    float acc[4][4][4];
#pragma unroll
    for (int i = 0; i < 4; i++)
#pragma unroll
        for (int j = 0; j < 4; j++)
#pragma unroll
            for (int q = 0; q < 4; q++) acc[i][j][q] = 0.f;

    float bias[4][2];
#pragma unroll
    for (int nt = 0; nt < 4; nt++) {
        int col = n0 + wn * 32 + nt * 8 + tq * 2;
        bias[nt][0] = bih[col] + bhh[col];
        bias[nt][1] = bih[col + 1] + bhh[col + 1];
    }

    {
        float4 av = *(const float4*)(A + (size_t)(m0 + srow) * K + skk);
        const float aa[4] = {av.x, av.y, av.z, av.w};
#pragma unroll
        for (int j = 0; j < 4; j++) {
            float h = __uint_as_float(f2tf32(aa[j]));
            *(float2*)&Ahl[0][srow][skk + j][0] = make_float2(h, aa[j] - h);
        }
        const float4* wv = (const float4*)(Whl + ((size_t)(n0 + srow) * K + skk) * 2);
        float4 w0 = wv[0], w1 = wv[1];
        *(float2*)&Bhl[0][srow][skk + 0][0] = make_float2(w0.x, w0.y);
        *(float2*)&Bhl[0][srow][skk + 1][0] = make_float2(w0.z, w0.w);
        *(float2*)&Bhl[0][srow][skk + 2][0] = make_float2(w1.x, w1.y);
        *(float2*)&Bhl[0][srow][skk + 3][0] = make_float2(w1.z, w1.w);
    }
    __syncthreads();

    const int NC = K / 8;
    for (int c = 0; c < NC; ++c) {
        const int cur = c & 1, nxt = cur ^ 1;
        float aa[4];
        float4 w0, w1;
        if (c + 1 < NC) {
            float4 av = *(const float4*)(A + (size_t)(m0 + srow) * K + (c + 1) * 8 + skk);
            aa[0] = av.x; aa[1] = av.y; aa[2] = av.z; aa[3] = av.w;
            const float4* wv = (const float4*)(Whl +
                ((size_t)(n0 + srow) * K + (c + 1) * 8 + skk) * 2);
            w0 = wv[0]; w1 = wv[1];
        }

        uint32_t bh[4][2], bl[4][2];
#pragma unroll
        for (int nt = 0; nt < 4; nt++) {
            int nr = wn * 32 + nt * 8 + gq;
            float2 v0 = *(const float2*)&Bhl[cur][nr][tq][0];
            float2 v1 = *(const float2*)&Bhl[cur][nr][tq + 4][0];
            bh[nt][0] = __float_as_uint(v0.x); bl[nt][0] = __float_as_uint(v0.y);
            bh[nt][1] = __float_as_uint(v1.x); bl[nt][1] = __float_as_uint(v1.y);
        }
#pragma unroll
        for (int mt = 0; mt < 4; mt++) {
            int mr = wm * 64 + mt * 16 + gq;
            float2 u0 = *(const float2*)&Ahl[cur][mr][tq][0];
            float2 u1 = *(const float2*)&Ahl[cur][mr + 8][tq][0];
            float2 u2 = *(const float2*)&Ahl[cur][mr][tq + 4][0];
            float2 u3 = *(const float2*)&Ahl[cur][mr + 8][tq + 4][0];
            uint32_t ah0 = __float_as_uint(u0.x), al0 = __float_as_uint(u0.y);
            uint32_t ah1 = __float_as_uint(u1.x), al1 = __float_as_uint(u1.y);
            uint32_t ah2 = __float_as_uint(u2.x), al2 = __float_as_uint(u2.y);
            uint32_t ah3 = __float_as_uint(u3.x), al3 = __float_as_uint(u3.y);
#pragma unroll
            for (int nt = 0; nt < 4; nt++) {
                float* cc = acc[mt][nt];
                mma_tf32(cc[0], cc[1], cc[2], cc[3],
                         ah0, ah1, ah2, ah3, bh[nt][0], bh[nt][1]);
                mma_tf32(cc[0], cc[1], cc[2], cc[3],
                         ah0, ah1, ah2, ah3, bl[nt][0], bl[nt][1]);
                mma_tf32(cc[0], cc[1], cc[2], cc[3],
                         al0, al1, al2, al3, bh[nt][0], bh[nt][1]);
            }
        }

        if (c + 1 < NC) {
#pragma unroll
            for (int j = 0; j < 4; j++) {
                float h = __uint_as_float(f2tf32(aa[j]));
                *(float2*)&Ahl[nxt][srow][skk + j][0] = make_float2(h, aa[j] - h);
            }
            *(float2*)&Bhl[nxt][srow][skk + 0][0] = make_float2(w0.x, w0.y);
            *(float2*)&Bhl[nxt][srow][skk + 1][0] = make_float2(w0.z, w0.w);
            *(float2*)&Bhl[nxt][srow][skk + 2][0] = make_float2(w1.x, w1.y);
            *(float2*)&Bhl[nxt][srow][skk + 3][0] = make_float2(w1.z, w1.w);
            __syncthreads();
        }
    }

#pragma unroll
    for (int mt = 0; mt < 4; mt++) {
        int row0 = m0 + wm * 64 + mt * 16 + gq;
#pragma unroll
        for (int nt = 0; nt < 4; nt++) {
            int col = n0 + wn * 32 + nt * 8 + tq * 2;
            float* cc = acc[mt][nt];
            *(float2*)(g_xg + (size_t)row0 * G4 + col) =
                make_float2(cc[0] + bias[nt][0], cc[1] + bias[nt][1]);
            *(float2*)(g_xg + (size_t)(row0 + 8) * G4 + col) =
                make_float2(cc[2] + bias[nt][0], cc[3] + bias[nt][1]);
        }
    }
}

// ---------------------------------------------------------------------------
// Recurrent chunk v17: R16 (direct peer-store) + R5-proven WAIT-AT-TOP.
// Gate warps send h(s) and arrive WITHOUT waiting; the flight overlaps
// sync2 + off-path work + loop overhead. At the top of step s, peer-k warps
// (kh != r, incl. gate warps) wait for parity (s-1)&1 before reading the
// peer half of hbuf[(s+1)&1]. Safety: our send at s targets parity s&1 on
// the peer; the peer's last read of that slot was its step s-1 matvec,
// proven complete by our top-of-s wait (mbarrier chain) — same argument
// that held for R5/R13.
// ---------------------------------------------------------------------------
__global__ __launch_bounds__(512, 1) __cluster_dims__(2, 1, 1)
void lstm_rec17(const float* __restrict__ whh0,
                const float* __restrict__ whh1,
                const float* __restrict__ whh2,
                float* __restrict__ hN, float* __restrict__ cN,
                int4 lsel, int4 tsel)
{
    __shared__ __align__(16) float hbuf[2][4][132];
    __shared__ __align__(16) float pre[2][256][4];
    __shared__ __align__(8)  ULL   bar;

    const int lc = blockIdx.y;
    const int l  = (lc == 0) ? lsel.x : (lc == 1) ? lsel.y : lsel.z;
    const int t0 = (lc == 0) ? tsel.x : (lc == 1) ? tsel.y : tsel.z;
    const float* whh = (l == 0) ? whh0 : (l == 1) ? whh1 : whh2;
    float* hstate = hN + l * BB * HH;
    float* cstate = cN + l * BB * HH;

    const int tid = threadIdx.x;
    const int r   = blockIdx.x & 1;
    const int b0  = (blockIdx.x >> 1) * 4;

    const int kh = tid >> 8;
    const int jp = tid & 255;
    const int g  = jp >> 6;
    const int nn = jp & 63;

    uint32_t bar_addr = smem_u32(&bar);
    uint32_t peer_bar = mapa_u32(bar_addr, (uint32_t)(r ^ 1));

    if (tid == 0) {
        asm volatile("mbarrier.init.shared.b64 [%0], %1;"
                     :: "r"(bar_addr), "r"(8) : "memory");
    }
    {
        int row = tid >> 7, n = tid & 127;
        hbuf[1][row][n] = hstate[(b0 + row) * HH + n];
    }

    const int row_w = g * 128 + r * 64 + nn;
    ULL w2[32];
    const ULL* wp = (const ULL*)(whh + (size_t)row_w * HH + kh * 64);
#pragma unroll
    for (int i = 0; i < 32; i++) w2[i] = wp[i];

    const bool is_gate = (kh == (r ^ 1));
    const int row_g = jp & 3;
    const int nn_g  = jp >> 2;
    const int n_g   = r * 64 + nn_g;

    float c = 0.f, hlast = 0.f;
    const float* px = g_xg + ((size_t)(b0 + row_g) * TT) * G4 + n_g;
    float*       py = g_y  + ((size_t)(b0 + row_g) * TT) * HH + n_g;
    uint32_t pl0 = 0, pl1 = 0;   // peer hbuf slots (our column, their buffer)
    float xc0=0,xc1=0,xc2=0,xc3=0, xn0=0,xn1=0,xn2=0,xn3=0;
    if (is_gate) {
        c   = cstate[(b0 + row_g) * HH + n_g];
        pl0 = mapa_u32(smem_u32(&hbuf[0][row_g][n_g]), (uint32_t)(r ^ 1));
        pl1 = mapa_u32(smem_u32(&hbuf[1][row_g][n_g]), (uint32_t)(r ^ 1));
        const float* p0 = px + (size_t)t0 * G4;
        xc0 = p0[0];        xc1 = p0[128];        xc2 = p0[256];        xc3 = p0[384];
        xn0 = p0[G4 + 0];   xn1 = p0[G4 + 128];   xn2 = p0[G4 + 256];   xn3 = p0[G4 + 384];
    }

    __syncthreads();
    asm volatile("barrier.cluster.arrive.aligned;" ::: "memory");
    asm volatile("barrier.cluster.wait.aligned;"   ::: "memory");

    for (int s = 0; s < CHUNK; ++s) {
        const int t  = t0 + s;
        const int pr = (s + 1) & 1;
        const int pw = s & 1;

        // WAIT-AT-TOP: peer-k warps wait for peer h(s-1) before reading it
        if (kh != r && s > 0) {
            unsigned par = (unsigned)((s - 1) & 1);
            asm volatile(
                "{\n\t"
                ".reg .pred P1;\n\t"
                "WLP%=:\n\t"
                "mbarrier.try_wait.parity.acquire.cluster.shared::cta.b64 P1, [%0], %1, 0x989680;\n\t"
                "@!P1 bra WLP%=;\n\t"
                "}"
                :: "r"(bar_addr), "r"(par) : "memory");
        }

        float s4[4];
#pragma unroll
        for (int rr = 0; rr < 4; rr += 2) {
            ULL a0 = 0, a1 = 0, c0_ = 0, c1_ = 0;
            const ulonglong2* hA = (const ulonglong2*)&hbuf[pr][rr][kh * 64];
            const ulonglong2* hB = (const ulonglong2*)&hbuf[pr][rr + 1][kh * 64];
#pragma unroll
            for (int i = 0; i < 16; i++) {
                ulonglong2 uA = hA[i], uB = hB[i];
                fma2(a0,  w2[2 * i],     uA.x);
                fma2(a1,  w2[2 * i + 1], uA.y);
                fma2(c0_, w2[2 * i],     uB.x);
                fma2(c1_, w2[2 * i + 1], uB.y);
            }
            float x0, x1, x2, x3;
            upk2(a0, x0, x1); upk2(a1, x2, x3);
            s4[rr] = (x0 + x1) + (x2 + x3);
            upk2(c0_, x0, x1); upk2(c1_, x2, x3);
            s4[rr + 1] = (x0 + x1) + (x2 + x3);
        }
        *(float4*)&pre[kh][jp][0] = make_float4(s4[0], s4[1], s4[2], s4[3]);
        __syncthreads();

        if (is_gate) {
            float pi = pre[0][      nn_g][row_g] + pre[1][      nn_g][row_g];
            float pf = pre[0][ 64 + nn_g][row_g] + pre[1][ 64 + nn_g][row_g];
            float pg = pre[0][128 + nn_g][row_g] + pre[1][128 + nn_g][row_g];
            float po = pre[0][192 + nn_g][row_g] + pre[1][192 + nn_g][row_g];
            float iv = sigapx(pi + xc0);
            float fv = sigapx(pf + xc1);
            float gv = tanhapx(pg + xc2);
            float ov = sigapx(po + xc3);
            c = fv * c + iv * gv;
            float hh = ov * tanhapx(c);
            hlast = hh;
            // fire the flight; do NOT wait here (wait happens at next loop top)
            uint32_t pa = pw ? pl1 : pl0;
            asm volatile("st.shared::cluster.f32 [%0], %1;"
                         :: "r"(pa), "f"(hh) : "memory");
            hbuf[pw][row_g][n_g] = hh;
            __syncwarp();
            if ((tid & 31) == 0) {
                asm volatile("mbarrier.arrive.release.cluster.shared::cluster.b64 _, [%0];"
                             :: "r"(peer_bar) : "memory");
            }
        }
        __syncthreads();

        if (is_gate) {
            py[(size_t)t * HH] = hlast;
            float xf0 = 0, xf1 = 0, xf2 = 0, xf3 = 0;
            if (s + 2 < CHUNK) {
                const float* p2 = px + (size_t)(t + 2) * G4;
                xf0 = p2[0]; xf1 = p2[128]; xf2 = p2[256]; xf3 = p2[384];
            }
            xc0 = xn0; xc1 = xn1; xc2 = xn2; xc3 = xn3;
            xn0 = xf0; xn1 = xf1; xn2 = xf2; xn3 = xf3;
        }
    }

    if (is_gate) {
        hstate[(b0 + row_g) * HH + n_g] = hlast;
        cstate[(b0 + row_g) * HH + n_g] = c;
    }
    asm volatile("barrier.cluster.arrive.aligned;" ::: "memory");
    asm volatile("barrier.cluster.wait.aligned;"   ::: "memory");
}

// ---------------------------------------------------------------------------
// Chunked output projection: rows b*TT + t0 + [0,CHUNK)
// ---------------------------------------------------------------------------
__global__ __launch_bounds__(256)
void proj_chunk(const float* __restrict__ wout,
                const float* __restrict__ bout,
                float* __restrict__ out, int t0)
{
    int gw   = (blockIdx.x * blockDim.x + threadIdx.x) >> 5;
    int lane = threadIdx.x & 31;
    if (gw >= BB * CHUNK) return;
    int b = gw >> 7;
    int t = gw & 127;
    size_t row = (size_t)b * TT + t0 + t;
    float4 yv = ((const float4*)(g_y + row * HH))[lane];
    float4 wv = ((const float4*)wout)[lane];
    float s = yv.x * wv.x + yv.y * wv.y + yv.z * wv.z + yv.w * wv.w;
#pragma unroll
    for (int o = 16; o; o >>= 1) s += __shfl_xor_sync(0xFFFFFFFFu, s, o);
    if (lane == 0) out[row] = fmaxf(s + bout[0], 0.f);
}

// ---------------------------------------------------------------------------
// R16 schedule (passing) with lstm_rec17.
// ---------------------------------------------------------------------------
extern "C" void kernel_launch(void* const* d_in, const int* in_sizes, int n_in,
                              void* d_out, int out_size)
{
    const float* x    = (const float*)d_in[0];
    const float* h0   = (const float*)d_in[1];
    const float* c0   = (const float*)d_in[2];
    const float* Wih[3] = {(const float*)d_in[3], (const float*)d_in[7],  (const float*)d_in[11]};
    const float* Whh[3] = {(const float*)d_in[4], (const float*)d_in[8],  (const float*)d_in[12]};
    const float* bih[3] = {(const float*)d_in[5], (const float*)d_in[9],  (const float*)d_in[13]};
    const float* bhh[3] = {(const float*)d_in[6], (const float*)d_in[10], (const float*)d_in[14]};
    const float* Wout = (const float*)d_in[15];
    const float* bout = (const float*)d_in[16];

    float* out = (float*)d_out;
    float* hN  = out + MROWS;
    float* cN  = hN + 3 * BB * HH;

    static cudaStream_t s2 = nullptr;
    static cudaEvent_t evPre, evWc, evPj, evW[13], evG0[8], evC[13];
    if (!s2) {
        cudaStreamCreateWithFlags(&s2, cudaStreamNonBlocking);
        cudaEventCreateWithFlags(&evPre, cudaEventDisableTiming);
        cudaEventCreateWithFlags(&evWc,  cudaEventDisableTiming);
        cudaEventCreateWithFlags(&evPj,  cudaEventDisableTiming);
        for (int i = 0; i < 13; i++) {
            cudaEventCreateWithFlags(&evW[i], cudaEventDisableTiming);
            cudaEventCreateWithFlags(&evC[i], cudaEventDisableTiming);
        }
        for (int i = 0; i < 8; i++)
            cudaEventCreateWithFlags(&evG0[i], cudaEventDisableTiming);
    }

    const int C = CHUNK;
    auto rec1 = [&](int l0_, int t0_) {
        lstm_rec17<<<dim3(64, 1), 512>>>(Whh[0], Whh[1], Whh[2], hN, cN,
                                         make_int4(l0_, 0, 0, 0),
                                         make_int4(t0_, 0, 0, 0));
    };
    auto rec2 = [&](int la, int ta, int lb, int tb) {
        lstm_rec17<<<dim3(64, 2), 512>>>(Whh[0], Whh[1], Whh[2], hN, cN,
                                         make_int4(la, lb, 0, 0),
                                         make_int4(ta, tb, 0, 0));
    };
    auto gemmM = [&](int l, int cc) {
        xg_tf32<128><<<dim3(4, 128), 256>>>(nullptr, 1, l, bih[l], bhh[l],
                                            cc * C, 0);
    };
    auto gemmS = [&](int l, int cc) {
        xg_tf32<128><<<dim3(4, 128), 256, 0, s2>>>(nullptr, 1, l, bih[l],
                                                   bhh[l], cc * C, 0);
    };
    auto gemm0S = [&](int cc) {
        xg_tf32<64><<<dim3(4, 128), 256, 0, s2>>>(x, 0, 0, bih[0], bhh[0],
                                                  cc * C, 0);
    };
    auto projS = [&](int cc) {
        proj_chunk<<<BB * C / 8, 256, 0, s2>>>(Wout, bout, out, cc * C);
    };

    // prologue
    init_state<<<(3 * BB * HH + 511) / 512, 512>>>(h0, c0, hN, cN);
    w_conv<<<(512 * 64 + 255) / 256, 256>>>(Wih[0], 0, 512 * 64);
    cudaEventRecord(evPre, 0);
    xg_tf32<64><<<dim3(4, 128), 256>>>(x, 0, 0, bih[0], bhh[0], 0, 0); // g0(0)

    cudaStreamWaitEvent(s2, evPre, 0);
    w_conv<<<(512 * 128 + 255) / 256, 256, 0, s2>>>(Wih[1], 1, 512 * 128);
    w_conv<<<(512 * 128 + 255) / 256, 256, 0, s2>>>(Wih[2], 2, 512 * 128);
    cudaEventRecord(evWc, s2);
    for (int cc = 1; cc < 8; cc++) { gemm0S(cc); cudaEventRecord(evG0[cc], s2); }

    // ---- walls ----
    rec1(0, 0);                                   // w0
    cudaStreamWaitEvent(0, evWc, 0);
    gemmM(1, 0);
    cudaStreamWaitEvent(0, evG0[1], 0);
    rec2(0, 1 * C, 1, 0 * C);                     // w1
    cudaEventRecord(evW[1], 0);
    gemmM(1, 1);

    cudaStreamWaitEvent(s2, evW[1], 0);
    gemmS(2, 0); cudaEventRecord(evC[3], s2);

    cudaStreamWaitEvent(0, evG0[2], 0);
    rec2(0, 2 * C, 1, 1 * C);                     // w2
    cudaEventRecord(evW[2], 0);

    cudaStreamWaitEvent(s2, evW[2], 0);
    gemmS(1, 2); cudaEventRecord(evC[4], s2);
    gemmS(2, 1); cudaEventRecord(evC[5], s2);

    cudaStreamWaitEvent(0, evG0[3], 0);
    cudaStreamWaitEvent(0, evC[3], 0);
    rec2(0, 3 * C, 2, 0 * C);                     // w3
    cudaEventRecord(evW[3], 0);

    cudaStreamWaitEvent(s2, evW[3], 0);
    gemmS(1, 3); cudaEventRecord(evC[6], s2);

    cudaStreamWaitEvent(0, evG0[4], 0);
    cudaStreamWaitEvent(0, evC[4], 0);
    rec2(0, 4 * C, 1, 2 * C);                     // w4
    cudaEventRecord(evW[4], 0);

    cudaStreamWaitEvent(s2, evW[4], 0);
    gemmS(2, 2); cudaEventRecord(evC[7], s2);
    gemmS(1, 4);

    cudaStreamWaitEvent(0, evG0[5], 0);
    cudaStreamWaitEvent(0, evC[5], 0);
    rec2(0, 5 * C, 2, 1 * C);                     // w5
    cudaEventRecord(evW[5], 0);

    cudaStreamWaitEvent(s2, evW[5], 0);
    gemmS(1, 5); cudaEventRecord(evC[9], s2);

    cudaStreamWaitEvent(0, evG0[6], 0);
    cudaStreamWaitEvent(0, evC[6], 0);
    rec2(0, 6 * C, 1, 3 * C);                     // w6
    cudaEventRecord(evW[6], 0);

    cudaStreamWaitEvent(s2, evW[6], 0);
    gemmS(2, 3); cudaEventRecord(evC[8], s2);
    gemmS(1, 6); cudaEventRecord(evC[10], s2);

    cudaStreamWaitEvent(0, evG0[7], 0);
    cudaStreamWaitEvent(0, evC[7], 0);
    rec2(0, 7 * C, 2, 2 * C);                     // w7
    cudaEventRecord(evW[7], 0);

    cudaStreamWaitEvent(s2, evW[7], 0);
    gemmS(1, 7); cudaEventRecord(evC[11], s2);

    cudaStreamWaitEvent(s2, evW[3], 0);  projS(0);
    cudaStreamWaitEvent(s2, evW[5], 0);  projS(1);

    cudaStreamWaitEvent(0, evC[8], 0);
    rec2(1, 4 * C, 2, 3 * C);                     // w8
    cudaEventRecord(evW[8], 0);
    gemmM(2, 4);

    cudaStreamWaitEvent(s2, evW[7], 0);  projS(2);
    cudaStreamWaitEvent(s2, evW[8], 0);  projS(3);

    cudaStreamWaitEvent(0, evC[9], 0);
    rec2(1, 5 * C, 2, 4 * C);                     // w9
    cudaEventRecord(evW[9], 0);
    gemmM(2, 5);

    cudaStreamWaitEvent(s2, evW[9], 0);  projS(4);

    cudaStreamWaitEvent(0, evC[10], 0);
    rec2(1, 6 * C, 2, 5 * C);                     // w10
    cudaEventRecord(evW[10], 0);
    gemmM(2, 6);

    cudaStreamWaitEvent(s2, evW[10], 0); projS(5);

    cudaStreamWaitEvent(0, evC[11], 0);
    rec2(1, 7 * C, 2, 6 * C);                     // w11
    cudaEventRecord(evW[11], 0);
    gemmM(2, 7);

    cudaStreamWaitEvent(s2, evW[11], 0); projS(6);
    cudaEventRecord(evPj, s2);

    rec1(2, 7 * C);                               // w12

    cudaStreamWaitEvent(0, evPj, 0);
    proj_chunk<<<BB * C / 8, 256>>>(Wout, bout, out, 7 * C);  // proj(7)
}